// round 2
// baseline (speedup 1.0000x reference)
#include <cuda_runtime.h>

// Depthwise conv_transpose2d(stride=4, k=7, bilinear) == separable x4 upsample.
// Input  x: [4, 256, 64, 64] fp32, Output: [4, 256, 259, 259] fp32.
//
// Unified tap algebra (p = o mod 4, a = o div 4):
//   out[o] = wA * in[a-1] + wB * in[a],  wA = 0.75 - 0.25*p, wB = 1 - wA
// (p=3 degenerates to identity on in[a]; OOB taps read as 0.)
// Separable: vertical blend first (2 rows), then horizontal (2 cols per ox).
//
// Each thread writes ONE aligned float4 of ONE output row. Because the row
// base alignment varies per (plane, oy)  (row pitch 1036 B), the 4-wide
// groups are shifted by off = rowstart_float_idx & 3 so that the vector
// store address is 16B-aligned. Ragged head/tail threads store scalars.

namespace {
constexpr int H = 64, W = 64;
constexpr int OH = 259, OW = 259;
constexpr int PLANES = 4 * 256;              // 1024
constexpr int GROUPS = 66;                   // float4 groups per row (incl. ragged ends)
constexpr int PER_PLANE = OH * GROUPS;       // 17094
constexpr int THREADS = 256;
constexpr int BLK_X = (PER_PLANE + THREADS - 1) / THREADS;  // 67
}

__global__ void __launch_bounds__(THREADS)
bilinear_up4_vec_kernel(const float* __restrict__ x, float* __restrict__ out) {
    int tp = blockIdx.x * THREADS + threadIdx.x;
    if (tp >= PER_PLANE) return;
    int plane = blockIdx.y;

    int oy = tp / GROUPS;
    int g  = tp - oy * GROUPS;

    const float* __restrict__ xp = x + (size_t)plane * (H * W);
    size_t rowstart = (size_t)plane * ((size_t)OH * OW) + (size_t)oy * OW;

    int off = (int)(rowstart & 3);           // floats to shift for 16B alignment
    int ox0 = 4 * g - off;                   // first output col of this thread

    // ---- vertical blend weights (rows a-1, a) ----
    int a  = oy >> 2;
    int py = oy & 3;
    float wyA = 0.75f - 0.25f * (float)py;
    float wyB = 1.0f - wyA;
    int  rA   = a - 1;
    bool rAok = (rA >= 0);
    bool rBok = (a < H);

    const float* rowA = xp + rA * W;
    const float* rowB = xp + a  * W;

    // ---- load 3 input columns, vertically blended ----
    int b0 = ox0 >> 2;                       // arithmetic shift (ox0 may be -1..-3)
    float v[3];
#pragma unroll
    for (int i = 0; i < 3; i++) {
        int c = b0 - 1 + i;
        bool cok = ((unsigned)c < (unsigned)W);
        float xa = (rAok && cok) ? __ldg(rowA + c) : 0.0f;
        float xb = (rBok && cok) ? __ldg(rowB + c) : 0.0f;
        v[i] = wyA * xa + wyB * xb;
    }

    // ---- horizontal blend: 4 consecutive outputs ----
    float o[4];
#pragma unroll
    for (int j = 0; j < 4; j++) {
        int ox = ox0 + j;                    // may be <0 or >=OW at ragged ends
        int b  = ox >> 2;
        int px = ox & 3;                     // two's-complement & == floor-mod
        float wxA = 0.75f - 0.25f * (float)px;
        float wxB = 1.0f - wxA;
        int i = b - b0;                      // 0 or 1
        o[j] = wxA * v[i] + wxB * v[i + 1];
    }

    float* dst = out + rowstart + ox0;
    if (ox0 >= 0 && ox0 + 3 < OW) {
        // interior: 16B-aligned vector store, evict-first (write-once stream)
        __stcs(reinterpret_cast<float4*>(dst), make_float4(o[0], o[1], o[2], o[3]));
    } else {
#pragma unroll
        for (int j = 0; j < 4; j++) {
            int ox = ox0 + j;
            if ((unsigned)ox < (unsigned)OW) __stcs(dst + j, o[j]);
        }
    }
}

extern "C" void kernel_launch(void* const* d_in, const int* in_sizes, int n_in,
                              void* d_out, int out_size) {
    const float* x = (const float*)d_in[0];
    float* out = (float*)d_out;
    (void)in_sizes; (void)n_in; (void)out_size;

    dim3 grid(BLK_X, PLANES);
    bilinear_up4_vec_kernel<<<grid, THREADS>>>(x, out);
}